// round 14
// baseline (speedup 1.0000x reference)
#include <cuda_runtime.h>
#include <cuda_bf16.h>
#include <math.h>
#include <stdint.h>

// Problem constants (fixed shapes)
#define S_LEN 1024
#define BATCH 8
#define EMB   1024
#define HEADS 16
#define HDIM  64
#define MROWS (S_LEN * BATCH)   // 8192
#define F3    (3 * EMB)         // 3072
#define NSB   (S_LEN / 128)     // 8 s-blocks per (b,h)
#define NTILE 16                // 1024/64 t-tiles

// -------- scratch (__device__ globals; no cudaMalloc allowed) --------
__device__ float g_qkv[MROWS * F3];
__device__ float g_ctx[MROWS * EMB];
__device__ float g_colsum[BATCH * S_LEN];
__device__ float g_lfv[BATCH * HEADS * S_LEN];   // row sums (no-max softmax)
__device__ float g_X  [BATCH * EMB];             // weighted-pooled ctx
__device__ float g_xc [MROWS * EMB];             // tf32-rounded x
__device__ float g_wc [F3 * EMB];                // tf32-rounded w_in

// ===========================================================================
// helpers: cp.async + tf32 mma.sync
// ===========================================================================
__device__ __forceinline__ uint32_t smem_u32(const void* p) {
    return (uint32_t)__cvta_generic_to_shared(p);
}
#define CP_ASYNC16(dst, src) \
    asm volatile("cp.async.cg.shared.global [%0], [%1], 16;" :: "r"(dst), "l"(src))
#define CP_ASYNC_COMMIT() asm volatile("cp.async.commit_group;" ::: "memory")
#define CP_ASYNC_WAIT(n)  asm volatile("cp.async.wait_group %0;" :: "n"(n) : "memory")

__device__ __forceinline__ uint32_t f2tf32(float f) {
    uint32_t u;
    asm("cvt.rna.tf32.f32 %0, %1;" : "=r"(u) : "f"(f));
    return u;
}
__device__ __forceinline__ float tf32f(float f) {
    return __uint_as_float(f2tf32(f));
}

__device__ __forceinline__ void mma_tf32(float* c, const uint32_t* a, const uint32_t* b) {
    asm volatile(
        "mma.sync.aligned.m16n8k8.row.col.f32.tf32.tf32.f32 "
        "{%0,%1,%2,%3}, {%4,%5,%6,%7}, {%8,%9}, {%0,%1,%2,%3};"
        : "+f"(c[0]), "+f"(c[1]), "+f"(c[2]), "+f"(c[3])
        : "r"(a[0]), "r"(a[1]), "r"(a[2]), "r"(a[3]), "r"(b[0]), "r"(b[1]));
}

// ===========================================================================
// zero kernel: colsum + X
// ===========================================================================
__global__ void zero_kernel() {
    int i = blockIdx.x * 256 + threadIdx.x;
    if (i < BATCH * S_LEN) g_colsum[i] = 0.0f;
    if (i < BATCH * EMB)   g_X[i] = 0.0f;
}

// ===========================================================================
// tf32 pre-convert (gmem -> gmem), float4 granularity
// ===========================================================================
__global__ __launch_bounds__(256) void cvt_kernel(
    const float4* __restrict__ src, float4* __restrict__ dst, int n4)
{
    int i = blockIdx.x * 256 + threadIdx.x;
    if (i < n4) {
        float4 v = src[i];
        v.x = tf32f(v.x); v.y = tf32f(v.y);
        v.z = tf32f(v.z); v.w = tf32f(v.w);
        dst[i] = v;
    }
}

// ===========================================================================
// tf32 tensor-core GEMM: 128x128 tile, BK=32, 3-stage cp.async (unchanged
// pipeline), but 512 threads (16 warps, warp tile 32x32) -> 32 warps/SM at
// 2 CTAs/SM. acc 32 regs/thread fits the 64-reg cap.
// ===========================================================================
#define TSTAGES 3
#define TBK 32
#define TLDS 36
#define TILE_FLOATS (128 * TLDS)
#define STAGE_FLOATS (2 * TILE_FLOATS)
#define STAGE_BYTES (STAGE_FLOATS * 4)
#define GEMM_SMEM (TSTAGES * STAGE_BYTES)

__global__ __launch_bounds__(512, 2) void tc_gemm(
    const float* __restrict__ A, const float* __restrict__ B,
    const float* __restrict__ bias, float* __restrict__ C,
    int M, int N, int K)
{
    extern __shared__ __align__(16) float smem[];
    const uint32_t sbase = smem_u32(smem);

    const int tid  = threadIdx.x;
    const int wid  = tid >> 5;        // 0..15
    const int lane = tid & 31;
    const int wr = wid >> 2;          // 0..3 (32-row band)
    const int wc = wid & 3;           // 0..3 (32-col band)
    const int qrow = lane >> 2;       // 0..7
    const int qcol = lane & 3;        // 0..3

    const int m0 = blockIdx.y * 128;
    const int n0 = blockIdx.x * 128;
    const int KT = K / TBK;

    // loader: threads <256 stage A, >=256 stage B
    const int opsel = tid >> 8;               // 0 = A, 1 = B
    const int lidx  = tid & 255;
    const int grow  = lidx >> 1;              // 0..127
    const int ghalf = lidx & 1;
    const float* Gp = (opsel ? B : A) + (size_t)((opsel ? n0 : m0) + grow) * K + ghalf * 16;
    const uint32_t srow = sbase + (uint32_t)(opsel ? TILE_FLOATS * 4 : 0)
                        + (grow * TLDS + ghalf * 16) * 4;

    #pragma unroll
    for (int p = 0; p < TSTAGES - 1; p++) {
        uint32_t so = (uint32_t)(p * STAGE_BYTES);
        #pragma unroll
        for (int i = 0; i < 4; i++)
            CP_ASYNC16(srow + so + i * 16, Gp + p * TBK + i * 4);
        CP_ASYNC_COMMIT();
    }

    float acc[2][4][4] = {};

    for (int kt = 0; kt < KT; kt++) {
        if (kt < KT - 1) { CP_ASYNC_WAIT(1); } else { CP_ASYNC_WAIT(0); }
        __syncthreads();

        if (kt + 2 < KT) {
            uint32_t so = (uint32_t)(((kt + 2) % TSTAGES) * STAGE_BYTES);
            #pragma unroll
            for (int i = 0; i < 4; i++)
                CP_ASYNC16(srow + so + i * 16, Gp + (kt + 2) * TBK + i * 4);
            CP_ASYNC_COMMIT();
        }

        const float* As = smem + (kt % TSTAGES) * STAGE_FLOATS;
        const float* Bs = As + TILE_FLOATS;

        #pragma unroll
        for (int ks = 0; ks < 4; ks++) {
            const int k0 = ks * 8 + qcol;
            uint32_t afr[2][4];
            uint32_t bfr[4][2];
            #pragma unroll
            for (int mt = 0; mt < 2; mt++) {
                const float* ar = As + (wr * 32 + mt * 16 + qrow) * TLDS;
                afr[mt][0] = __float_as_uint(ar[k0]);
                afr[mt][1] = __float_as_uint(ar[8 * TLDS + k0]);
                afr[mt][2] = __float_as_uint(ar[k0 + 4]);
                afr[mt][3] = __float_as_uint(ar[8 * TLDS + k0 + 4]);
            }
            #pragma unroll
            for (int nt = 0; nt < 4; nt++) {
                const float* br = Bs + (wc * 32 + nt * 8 + qrow) * TLDS;
                bfr[nt][0] = __float_as_uint(br[k0]);
                bfr[nt][1] = __float_as_uint(br[k0 + 4]);
            }
            #pragma unroll
            for (int mt = 0; mt < 2; mt++)
                #pragma unroll
                for (int nt = 0; nt < 4; nt++)
                    mma_tf32(acc[mt][nt], afr[mt], bfr[nt]);
        }
    }

    __syncthreads();
    #pragma unroll
    for (int mt = 0; mt < 2; mt++) {
        int row = m0 + wr * 32 + mt * 16 + qrow;
        #pragma unroll
        for (int nt = 0; nt < 4; nt++) {
            int col = n0 + wc * 32 + nt * 8 + 2 * qcol;
            float b0 = bias[col], b1 = bias[col + 1];
            float2 o0 = make_float2(acc[mt][nt][0] + b0, acc[mt][nt][1] + b1);
            float2 o1 = make_float2(acc[mt][nt][2] + b0, acc[mt][nt][3] + b1);
            *(float2*)&C[(size_t)row * N + col] = o0;
            *(float2*)&C[(size_t)(row + 8) * N + col] = o1;
        }
    }
}

// ===========================================================================
// Attention pass 1 (no-max softmax, R13 version): unnormalized U and l;
// ctx = U/l at the end.
// ===========================================================================
#define QD 68
#define KD 68
#define VD 72
#define PD 68
#define P1_SMEM ((128*QD + 64*KD + 64*VD + 128*PD) * 4)

__global__ __launch_bounds__(256, 2) void attn_pass1(
    const float* __restrict__ qkv, float* __restrict__ ctx)
{
    extern __shared__ __align__(16) float sm[];
    float* Qs = sm;
    float* Ks = Qs + 128 * QD;
    float* Vs = Ks + 64 * KD;
    float* Ps = Vs + 64 * VD;

    const int tid  = threadIdx.x;
    const int wid  = tid >> 5;
    const int lane = tid & 31;
    const int qrow = lane >> 2;
    const int q    = lane & 3;
    const int sb = blockIdx.x, h = blockIdx.y, b = blockIdx.z;
    const int s0 = sb * 128;
    const int R0 = wid * 16 + qrow;

    for (int idx = tid; idx < 128 * 16; idx += 256) {
        int row = idx >> 4, c = idx & 15;
        float4 v = *(const float4*)&qkv[((size_t)(s0 + row) * BATCH + b) * F3 + h * HDIM + c * 4];
        float4 o = make_float4(tf32f(v.x * 0.125f), tf32f(v.y * 0.125f),
                               tf32f(v.z * 0.125f), tf32f(v.w * 0.125f));
        *(float4*)&Qs[row * QD + c * 4] = o;
    }

    float l0 = 0.0f, l1 = 0.0f;
    float acc[8][4] = {};
    __syncthreads();

    for (int tb = 0; tb < NTILE; tb++) {
        const int t0 = tb * 64;
        for (int idx = tid; idx < 64 * 16; idx += 256) {
            int row = idx >> 4, c = idx & 15;
            const float* base = &qkv[((size_t)(t0 + row) * BATCH + b) * F3 + h * HDIM + c * 4];
            float4 kv = *(const float4*)(base + EMB);
            float4 vv = *(const float4*)(base + 2 * EMB);
            *(float4*)&Ks[row * KD + c * 4] =
                make_float4(tf32f(kv.x), tf32f(kv.y), tf32f(kv.z), tf32f(kv.w));
            *(float4*)&Vs[row * VD + c * 4] =
                make_float4(tf32f(vv.x), tf32f(vv.y), tf32f(vv.z), tf32f(vv.w));
        }
        __syncthreads();

        float sf[8][4] = {};
        #pragma unroll
        for (int ks = 0; ks < 8; ks++) {
            const int kq = ks * 8 + q;
            uint32_t a[4];
            a[0] = __float_as_uint(Qs[R0 * QD + kq]);
            a[1] = __float_as_uint(Qs[(R0 + 8) * QD + kq]);
            a[2] = __float_as_uint(Qs[R0 * QD + kq + 4]);
            a[3] = __float_as_uint(Qs[(R0 + 8) * QD + kq + 4]);
            #pragma unroll
            for (int nt = 0; nt < 8; nt++) {
                uint32_t bb[2];
                bb[0] = __float_as_uint(Ks[(nt * 8 + qrow) * KD + kq]);
                bb[1] = __float_as_uint(Ks[(nt * 8 + qrow) * KD + kq + 4]);
                mma_tf32(sf[nt], a, bb);
            }
        }

        float rs0 = 0.0f, rs1 = 0.0f;
        #pragma unroll
        for (int nt = 0; nt < 8; nt++) {
            float p0 = __expf(sf[nt][0]);
            float p1 = __expf(sf[nt][1]);
            float p2 = __expf(sf[nt][2]);
            float p3 = __expf(sf[nt][3]);
            rs0 += p0 + p1;
            rs1 += p2 + p3;
            *(float2*)&Ps[R0 * PD + nt * 8 + 2 * q] =
                make_float2(tf32f(p0), tf32f(p1));
            *(float2*)&Ps[(R0 + 8) * PD + nt * 8 + 2 * q] =
                make_float2(tf32f(p2), tf32f(p3));
        }
        rs0 += __shfl_xor_sync(0xffffffffu, rs0, 1);
        rs0 += __shfl_xor_sync(0xffffffffu, rs0, 2);
        rs1 += __shfl_xor_sync(0xffffffffu, rs1, 1);
        rs1 += __shfl_xor_sync(0xffffffffu, rs1, 2);
        l0 += rs0;
        l1 += rs1;
        __syncwarp();

        #pragma unroll
        for (int ks = 0; ks < 8; ks++) {
            const int kq = ks * 8 + q;
            uint32_t a[4];
            a[0] = __float_as_uint(Ps[R0 * PD + kq]);
            a[1] = __float_as_uint(Ps[(R0 + 8) * PD + kq]);
            a[2] = __float_as_uint(Ps[R0 * PD + kq + 4]);
            a[3] = __float_as_uint(Ps[(R0 + 8) * PD + kq + 4]);
            #pragma unroll
            for (int nt = 0; nt < 8; nt++) {
                uint32_t bb[2];
                bb[0] = __float_as_uint(Vs[kq * VD + nt * 8 + qrow]);
                bb[1] = __float_as_uint(Vs[(kq + 4) * VD + nt * 8 + qrow]);
                mma_tf32(acc[nt], a, bb);
            }
        }
        __syncthreads();
    }

    const float inv0 = 1.0f / l0, inv1 = 1.0f / l1;
    #pragma unroll
    for (int nt = 0; nt < 8; nt++) {
        size_t base0 = ((size_t)(s0 + R0) * BATCH + b) * EMB + h * HDIM + nt * 8 + 2 * q;
        size_t base1 = ((size_t)(s0 + R0 + 8) * BATCH + b) * EMB + h * HDIM + nt * 8 + 2 * q;
        *(float2*)&ctx[base0] = make_float2(acc[nt][0] * inv0, acc[nt][1] * inv0);
        *(float2*)&ctx[base1] = make_float2(acc[nt][2] * inv1, acc[nt][3] * inv1);
    }

    if (q == 0) {
        int base = (b * HEADS + h) * S_LEN + s0;
        g_lfv[base + R0]     = l0;
        g_lfv[base + R0 + 8] = l1;
    }
}

// ===========================================================================
// Attention pass 2 (no-max, R13 version): colsum via QK^T recompute,
// p = exp(s)/l, shfl-reduce + gmem atomics. smem 52KB -> 4 CTAs/SM.
// ===========================================================================
#define P2_SMEM ((128*QD + 64*KD) * 4)

__global__ __launch_bounds__(256) void attn_pass2(
    const float* __restrict__ qkv, float* __restrict__ colsum)
{
    extern __shared__ __align__(16) float sm[];
    float* Qs = sm;
    float* Ks = Qs + 128 * QD;

    const int tid  = threadIdx.x;
    const int wid  = tid >> 5;
    const int lane = tid & 31;
    const int qrow = lane >> 2;
    const int q    = lane & 3;
    const int sb = blockIdx.x, h = blockIdx.y, b = blockIdx.z;
    const int s0 = sb * 128;
    const int R0 = wid * 16 + qrow;

    for (int idx = tid; idx < 128 * 16; idx += 256) {
        int row = idx >> 4, c = idx & 15;
        float4 v = *(const float4*)&qkv[((size_t)(s0 + row) * BATCH + b) * F3 + h * HDIM + c * 4];
        float4 o = make_float4(tf32f(v.x * 0.125f), tf32f(v.y * 0.125f),
                               tf32f(v.z * 0.125f), tf32f(v.w * 0.125f));
        *(float4*)&Qs[row * QD + c * 4] = o;
    }

    const int mlbase = (b * HEADS + h) * S_LEN + s0;
    const float inv0 = 1.0f / g_lfv[mlbase + R0];
    const float inv1 = 1.0f / g_lfv[mlbase + R0 + 8];

    for (int tb = 0; tb < NTILE; tb++) {
        const int t0 = tb * 64;
        __syncthreads();
        for (int idx = tid; idx < 64 * 16; idx += 256) {
            int row = idx >> 4, c = idx & 15;
            const float* base = &qkv[((size_t)(t0 + row) * BATCH + b) * F3 + h * HDIM + c * 4];
            float4 kv = *(const float4*)(base + EMB);
            *(float4*)&Ks[row * KD + c * 4] =
                make_float4(tf32f(kv.x), tf32f(kv.y), tf32f(kv.z), tf32f(kv.w));
        }
        __syncthreads();

        float sf[8][4] = {};
        #pragma unroll
        for (int ks = 0; ks < 8; ks++) {
            const int kq = ks * 8 + q;
            uint32_t a[4];
            a[0] = __float_as_uint(Qs[R0 * QD + kq]);
            a[1] = __float_as_uint(Qs[(R0 + 8) * QD + kq]);
            a[2] = __float_as_uint(Qs[R0 * QD + kq + 4]);
            a[3] = __float_as_uint(Qs[(R0 + 8) * QD + kq + 4]);
            #pragma unroll
            for (int nt = 0; nt < 8; nt++) {
                uint32_t bb[2];
                bb[0] = __float_as_uint(Ks[(nt * 8 + qrow) * KD + kq]);
                bb[1] = __float_as_uint(Ks[(nt * 8 + qrow) * KD + kq + 4]);
                mma_tf32(sf[nt], a, bb);
            }
        }

        #pragma unroll
        for (int nt = 0; nt < 8; nt++) {
            float p0 = __expf(sf[nt][0]) * inv0;
            float p1 = __expf(sf[nt][1]) * inv0;
            float p2 = __expf(sf[nt][2]) * inv1;
            float p3 = __expf(sf[nt][3]) * inv1;
            float v0 = p0 + p2, v1 = p1 + p3;
            #pragma unroll
            for (int off = 4; off <= 16; off <<= 1) {
                v0 += __shfl_xor_sync(0xffffffffu, v0, off);
                v1 += __shfl_xor_sync(0xffffffffu, v1, off);
            }
            if (qrow == 0) {
                atomicAdd(&colsum[b * S_LEN + t0 + nt * 8 + 2 * q],     v0);
                atomicAdd(&colsum[b * S_LEN + t0 + nt * 8 + 2 * q + 1], v1);
            }
        }
    }
}

// ===========================================================================
// wpool (R9 version, 256 CTAs): X[b,c] += sum over 128-t chunk
// ===========================================================================
__global__ __launch_bounds__(256) void wpool_kernel(
    const float* __restrict__ ctx, const float* __restrict__ colsum,
    float* __restrict__ X)
{
    const int b  = blockIdx.z;
    const int t0 = blockIdx.y * 128;
    const int c  = blockIdx.x * 256 + threadIdx.x;
    const float inv = 1.0f / ((float)S_LEN * (float)HEADS);
    float acc = 0.0f;
    #pragma unroll 4
    for (int t = t0; t < t0 + 128; t++) {
        float w = colsum[b * S_LEN + t] * inv;
        acc = fmaf(w, ctx[((size_t)t * BATCH + b) * EMB + c], acc);
    }
    atomicAdd(&X[b * EMB + c], acc);
}

// ===========================================================================
// gemv: out[b,e] = sum_c X[b,c]*W[e,c] + bias[e]
// ===========================================================================
__global__ __launch_bounds__(256) void gemv_kernel(
    const float* __restrict__ X, const float* __restrict__ W,
    const float* __restrict__ bias, float* __restrict__ out)
{
    const int wid  = threadIdx.x >> 5;
    const int lane = threadIdx.x & 31;
    const int e = blockIdx.x * 8 + wid;

    float acc[BATCH] = {};
    for (int c0 = lane * 4; c0 < EMB; c0 += 128) {
        float4 wv = *(const float4*)&W[(size_t)e * EMB + c0];
        #pragma unroll
        for (int b = 0; b < BATCH; b++) {
            float4 xv = *(const float4*)&X[b * EMB + c0];
            acc[b] += wv.x * xv.x + wv.y * xv.y + wv.z * xv.z + wv.w * xv.w;
        }
    }
    #pragma unroll
    for (int b = 0; b < BATCH; b++) {
        float v = acc[b];
        #pragma unroll
        for (int off = 16; off >= 1; off >>= 1)
            v += __shfl_xor_sync(0xffffffffu, v, off);
        if (lane == 0) out[b * EMB + e] = v + bias[e];
    }
}

// ===========================================================================
extern "C" void kernel_launch(void* const* d_in, const int* in_sizes, int n_in,
                              void* d_out, int out_size)
{
    const float* x     = (const float*)d_in[0];
    const float* w_in  = (const float*)d_in[1];
    const float* b_in  = (const float*)d_in[2];
    const float* w_out = (const float*)d_in[3];
    const float* b_out = (const float*)d_in[4];
    float* out = (float*)d_out;

    float *qkv_p, *ctx_p, *colsum_p, *X_p, *xc_p, *wc_p;
    cudaGetSymbolAddress((void**)&qkv_p,    g_qkv);
    cudaGetSymbolAddress((void**)&ctx_p,    g_ctx);
    cudaGetSymbolAddress((void**)&colsum_p, g_colsum);
    cudaGetSymbolAddress((void**)&X_p,      g_X);
    cudaGetSymbolAddress((void**)&xc_p,     g_xc);
    cudaGetSymbolAddress((void**)&wc_p,     g_wc);

    cudaFuncSetAttribute(attn_pass1, cudaFuncAttributeMaxDynamicSharedMemorySize,
                         P1_SMEM);
    cudaFuncSetAttribute(attn_pass2, cudaFuncAttributeMaxDynamicSharedMemorySize,
                         P2_SMEM);
    cudaFuncSetAttribute(tc_gemm, cudaFuncAttributeMaxDynamicSharedMemorySize,
                         GEMM_SMEM);

    zero_kernel<<<32, 256>>>();

    // pre-convert GEMM operands to tf32 (once per element, in gmem)
    cvt_kernel<<<(MROWS * EMB / 4 + 255) / 256, 256>>>(
        (const float4*)x, (float4*)xc_p, MROWS * EMB / 4);
    cvt_kernel<<<(F3 * EMB / 4 + 255) / 256, 256>>>(
        (const float4*)w_in, (float4*)wc_p, F3 * EMB / 4);

    // QKV projection (tf32 mma.sync, 512 threads, 32 warps/SM)
    tc_gemm<<<dim3(F3 / 128, MROWS / 128), 512, GEMM_SMEM>>>(
        xc_p, wc_p, b_in, qkv_p, MROWS, F3, EMB);

    // attention pass 1 (no-max): ctx + l
    attn_pass1<<<dim3(NSB, HEADS, BATCH), 256, P1_SMEM>>>(qkv_p, ctx_p);

    // attention pass 2 (no-max): colsum
    attn_pass2<<<dim3(NSB, HEADS, BATCH), 256, P2_SMEM>>>(qkv_p, colsum_p);

    // weighted pooling of ctx (pool-before-projection; exact by linearity)
    wpool_kernel<<<dim3(EMB / 256, S_LEN / 128, BATCH), 256>>>(
        ctx_p, colsum_p, X_p);

    // tiny GEMV against w_out (+ bias, since weights sum to 1)
    gemv_kernel<<<EMB / 8, 256>>>(X_p, w_out, b_out, out);
}

// round 15
// speedup vs baseline: 1.1368x; 1.1368x over previous
#include <cuda_runtime.h>
#include <cuda_bf16.h>
#include <math.h>
#include <stdint.h>

// Problem constants (fixed shapes)
#define S_LEN 1024
#define BATCH 8
#define EMB   1024
#define HEADS 16
#define HDIM  64
#define MROWS (S_LEN * BATCH)   // 8192
#define F3    (3 * EMB)         // 3072
#define NSB   (S_LEN / 128)     // 8 s-blocks per (b,h)
#define NCTA  (BATCH * HEADS * NSB)  // 1024
#define NTILE 16                // 1024/64 t-tiles

// -------- scratch (__device__ globals; no cudaMalloc allowed) --------
__device__ float g_qkv[MROWS * F3];
__device__ float g_ctx[MROWS * EMB];
__device__ float g_colsum[BATCH * S_LEN];
__device__ float g_lfv[BATCH * HEADS * S_LEN];   // row sums (no-max softmax)
__device__ float g_X  [BATCH * EMB];             // weighted-pooled ctx
__device__ float g_xc [MROWS * EMB];             // tf32-rounded x
__device__ float g_wc [F3 * EMB];                // tf32-rounded w_in
__device__ __nv_bfloat16 g_ps[(size_t)NCTA * 128 * S_LEN];  // prob spill, 268MB

// ===========================================================================
// helpers
// ===========================================================================
__device__ __forceinline__ uint32_t smem_u32(const void* p) {
    return (uint32_t)__cvta_generic_to_shared(p);
}
#define CP_ASYNC16(dst, src) \
    asm volatile("cp.async.cg.shared.global [%0], [%1], 16;" :: "r"(dst), "l"(src))
#define CP_ASYNC_COMMIT() asm volatile("cp.async.commit_group;" ::: "memory")
#define CP_ASYNC_WAIT(n)  asm volatile("cp.async.wait_group %0;" :: "n"(n) : "memory")

__device__ __forceinline__ uint32_t f2tf32(float f) {
    uint32_t u;
    asm("cvt.rna.tf32.f32 %0, %1;" : "=r"(u) : "f"(f));
    return u;
}
__device__ __forceinline__ float tf32f(float f) {
    return __uint_as_float(f2tf32(f));
}
__device__ __forceinline__ uint32_t pkbf(float a, float b) {
    __nv_bfloat162 t = __floats2bfloat162_rn(a, b);
    return *(uint32_t*)&t;
}

__device__ __forceinline__ void mma_tf32(float* c, const uint32_t* a, const uint32_t* b) {
    asm volatile(
        "mma.sync.aligned.m16n8k8.row.col.f32.tf32.tf32.f32 "
        "{%0,%1,%2,%3}, {%4,%5,%6,%7}, {%8,%9}, {%0,%1,%2,%3};"
        : "+f"(c[0]), "+f"(c[1]), "+f"(c[2]), "+f"(c[3])
        : "r"(a[0]), "r"(a[1]), "r"(a[2]), "r"(a[3]), "r"(b[0]), "r"(b[1]));
}

// ===========================================================================
// zero kernel: colsum + X
// ===========================================================================
__global__ void zero_kernel() {
    int i = blockIdx.x * 256 + threadIdx.x;
    if (i < BATCH * S_LEN) g_colsum[i] = 0.0f;
    if (i < BATCH * EMB)   g_X[i] = 0.0f;
}

// ===========================================================================
// tf32 pre-convert (gmem -> gmem), float4 granularity
// ===========================================================================
__global__ __launch_bounds__(256) void cvt_kernel(
    const float4* __restrict__ src, float4* __restrict__ dst, int n4)
{
    int i = blockIdx.x * 256 + threadIdx.x;
    if (i < n4) {
        float4 v = src[i];
        v.x = tf32f(v.x); v.y = tf32f(v.y);
        v.z = tf32f(v.z); v.w = tf32f(v.w);
        dst[i] = v;
    }
}

// ===========================================================================
// tf32 tensor-core GEMM (EXACT R9 passing version, ~521us)
// ===========================================================================
#define TSTAGES 3
#define TBK 32
#define TLDS 36
#define TILE_FLOATS (128 * TLDS)
#define STAGE_FLOATS (2 * TILE_FLOATS)
#define STAGE_BYTES (STAGE_FLOATS * 4)
#define GEMM_SMEM (TSTAGES * STAGE_BYTES)

__global__ __launch_bounds__(256) void tc_gemm(
    const float* __restrict__ A, const float* __restrict__ B,
    const float* __restrict__ bias, float* __restrict__ C,
    int M, int N, int K)
{
    extern __shared__ __align__(16) float smem[];
    const uint32_t sbase = smem_u32(smem);

    const int tid  = threadIdx.x;
    const int wid  = tid >> 5;
    const int lane = tid & 31;
    const int wr = wid >> 2;
    const int wc = wid & 3;
    const int qrow = lane >> 2;
    const int qcol = lane & 3;

    const int m0 = blockIdx.y * 128;
    const int n0 = blockIdx.x * 128;
    const int KT = K / TBK;

    const int grow = tid >> 1;
    const int ghalf = tid & 1;
    const float* Ag = A + (size_t)(m0 + grow) * K + ghalf * 16;
    const float* Bg = B + (size_t)(n0 + grow) * K + ghalf * 16;
    const uint32_t srowA = sbase + (grow * TLDS + ghalf * 16) * 4;
    const uint32_t srowB = srowA + TILE_FLOATS * 4;

    #pragma unroll
    for (int p = 0; p < TSTAGES - 1; p++) {
        uint32_t so = (uint32_t)(p * STAGE_BYTES);
        #pragma unroll
        for (int i = 0; i < 4; i++) {
            CP_ASYNC16(srowA + so + i * 16, Ag + p * TBK + i * 4);
            CP_ASYNC16(srowB + so + i * 16, Bg + p * TBK + i * 4);
        }
        CP_ASYNC_COMMIT();
    }

    float acc[4][4][4] = {};

    for (int kt = 0; kt < KT; kt++) {
        if (kt < KT - 1) { CP_ASYNC_WAIT(1); } else { CP_ASYNC_WAIT(0); }
        __syncthreads();

        if (kt + 2 < KT) {
            uint32_t so = (uint32_t)(((kt + 2) % TSTAGES) * STAGE_BYTES);
            #pragma unroll
            for (int i = 0; i < 4; i++) {
                CP_ASYNC16(srowA + so + i * 16, Ag + (kt + 2) * TBK + i * 4);
                CP_ASYNC16(srowB + so + i * 16, Bg + (kt + 2) * TBK + i * 4);
            }
            CP_ASYNC_COMMIT();
        }

        const float* As = smem + (kt % TSTAGES) * STAGE_FLOATS;
        const float* Bs = As + TILE_FLOATS;

        #pragma unroll
        for (int ks = 0; ks < 4; ks++) {
            const int k0 = ks * 8 + qcol;
            uint32_t afr[4][4];
            uint32_t bfr[4][2];
            #pragma unroll
            for (int mt = 0; mt < 4; mt++) {
                const float* ar = As + (wr * 64 + mt * 16 + qrow) * TLDS;
                afr[mt][0] = __float_as_uint(ar[k0]);
                afr[mt][1] = __float_as_uint(ar[8 * TLDS + k0]);
                afr[mt][2] = __float_as_uint(ar[k0 + 4]);
                afr[mt][3] = __float_as_uint(ar[8 * TLDS + k0 + 4]);
            }
            #pragma unroll
            for (int nt = 0; nt < 4; nt++) {
                const float* br = Bs + (wc * 32 + nt * 8 + qrow) * TLDS;
                bfr[nt][0] = __float_as_uint(br[k0]);
                bfr[nt][1] = __float_as_uint(br[k0 + 4]);
            }
            #pragma unroll
            for (int mt = 0; mt < 4; mt++)
                #pragma unroll
                for (int nt = 0; nt < 4; nt++)
                    mma_tf32(acc[mt][nt], afr[mt], bfr[nt]);
        }
    }

    __syncthreads();
    #pragma unroll
    for (int mt = 0; mt < 4; mt++) {
        int row = m0 + wr * 64 + mt * 16 + qrow;
        #pragma unroll
        for (int nt = 0; nt < 4; nt++) {
            int col = n0 + wc * 32 + nt * 8 + 2 * qcol;
            float b0 = bias[col], b1 = bias[col + 1];
            float2 o0 = make_float2(acc[mt][nt][0] + b0, acc[mt][nt][1] + b1);
            float2 o1 = make_float2(acc[mt][nt][2] + b0, acc[mt][nt][3] + b1);
            *(float2*)&C[(size_t)row * N + col] = o0;
            *(float2*)&C[(size_t)(row + 8) * N + col] = o1;
        }
    }
}

// ===========================================================================
// Attention pass 1 (no-max softmax): unnormalized U and l; ctx = U/l.
// NEW: spills unnormalized probs to global as bf16 (for the colsum kernel).
// ===========================================================================
#define QD 68
#define KD 68
#define VD 72
#define PD 68
#define P1_SMEM ((128*QD + 64*KD + 64*VD + 128*PD) * 4)

__global__ __launch_bounds__(256, 2) void attn_pass1(
    const float* __restrict__ qkv, float* __restrict__ ctx)
{
    extern __shared__ __align__(16) float sm[];
    float* Qs = sm;
    float* Ks = Qs + 128 * QD;
    float* Vs = Ks + 64 * KD;
    float* Ps = Vs + 64 * VD;

    const int tid  = threadIdx.x;
    const int wid  = tid >> 5;
    const int lane = tid & 31;
    const int qrow = lane >> 2;
    const int q    = lane & 3;
    const int sb = blockIdx.x, h = blockIdx.y, b = blockIdx.z;
    const int s0 = sb * 128;
    const int cta = (b * HEADS + h) * NSB + sb;
    const int R0 = wid * 16 + qrow;

    for (int idx = tid; idx < 128 * 16; idx += 256) {
        int row = idx >> 4, c = idx & 15;
        float4 v = *(const float4*)&qkv[((size_t)(s0 + row) * BATCH + b) * F3 + h * HDIM + c * 4];
        float4 o = make_float4(tf32f(v.x * 0.125f), tf32f(v.y * 0.125f),
                               tf32f(v.z * 0.125f), tf32f(v.w * 0.125f));
        *(float4*)&Qs[row * QD + c * 4] = o;
    }

    float l0 = 0.0f, l1 = 0.0f;
    float acc[8][4] = {};
    __syncthreads();

    for (int tb = 0; tb < NTILE; tb++) {
        const int t0 = tb * 64;
        for (int idx = tid; idx < 64 * 16; idx += 256) {
            int row = idx >> 4, c = idx & 15;
            const float* base = &qkv[((size_t)(t0 + row) * BATCH + b) * F3 + h * HDIM + c * 4];
            float4 kv = *(const float4*)(base + EMB);
            float4 vv = *(const float4*)(base + 2 * EMB);
            *(float4*)&Ks[row * KD + c * 4] =
                make_float4(tf32f(kv.x), tf32f(kv.y), tf32f(kv.z), tf32f(kv.w));
            *(float4*)&Vs[row * VD + c * 4] =
                make_float4(tf32f(vv.x), tf32f(vv.y), tf32f(vv.z), tf32f(vv.w));
        }
        __syncthreads();

        float sf[8][4] = {};
        #pragma unroll
        for (int ks = 0; ks < 8; ks++) {
            const int kq = ks * 8 + q;
            uint32_t a[4];
            a[0] = __float_as_uint(Qs[R0 * QD + kq]);
            a[1] = __float_as_uint(Qs[(R0 + 8) * QD + kq]);
            a[2] = __float_as_uint(Qs[R0 * QD + kq + 4]);
            a[3] = __float_as_uint(Qs[(R0 + 8) * QD + kq + 4]);
            #pragma unroll
            for (int nt = 0; nt < 8; nt++) {
                uint32_t bb[2];
                bb[0] = __float_as_uint(Ks[(nt * 8 + qrow) * KD + kq]);
                bb[1] = __float_as_uint(Ks[(nt * 8 + qrow) * KD + kq + 4]);
                mma_tf32(sf[nt], a, bb);
            }
        }

        float rs0 = 0.0f, rs1 = 0.0f;
        #pragma unroll
        for (int nt = 0; nt < 8; nt++) {
            float p0 = __expf(sf[nt][0]);
            float p1 = __expf(sf[nt][1]);
            float p2 = __expf(sf[nt][2]);
            float p3 = __expf(sf[nt][3]);
            rs0 += p0 + p1;
            rs1 += p2 + p3;
            *(float2*)&Ps[R0 * PD + nt * 8 + 2 * q] =
                make_float2(tf32f(p0), tf32f(p1));
            *(float2*)&Ps[(R0 + 8) * PD + nt * 8 + 2 * q] =
                make_float2(tf32f(p2), tf32f(p3));
        }
        rs0 += __shfl_xor_sync(0xffffffffu, rs0, 1);
        rs0 += __shfl_xor_sync(0xffffffffu, rs0, 2);
        rs1 += __shfl_xor_sync(0xffffffffu, rs1, 1);
        rs1 += __shfl_xor_sync(0xffffffffu, rs1, 2);
        l0 += rs0;
        l1 += rs1;
        __syncwarp();

        // U += P @ V (unnormalized)
        #pragma unroll
        for (int ks = 0; ks < 8; ks++) {
            const int kq = ks * 8 + q;
            uint32_t a[4];
            a[0] = __float_as_uint(Ps[R0 * PD + kq]);
            a[1] = __float_as_uint(Ps[(R0 + 8) * PD + kq]);
            a[2] = __float_as_uint(Ps[R0 * PD + kq + 4]);
            a[3] = __float_as_uint(Ps[(R0 + 8) * PD + kq + 4]);
            #pragma unroll
            for (int nt = 0; nt < 8; nt++) {
                uint32_t bb[2];
                bb[0] = __float_as_uint(Vs[kq * VD + nt * 8 + qrow]);
                bb[1] = __float_as_uint(Vs[(kq + 4) * VD + nt * 8 + qrow]);
                mma_tf32(acc[nt], a, bb);
            }
        }

        // spill own-warp probs (16 rows x 64 t) as bf16, coalesced 128B rows
        {
            __nv_bfloat16* gp = g_ps + ((size_t)cta * 128 + wid * 16) * S_LEN + t0;
            #pragma unroll
            for (int j = 0; j < 4; j++) {
                int srow = j * 4 + (lane >> 3);      // 0..15
                int tloc = (lane & 7) * 8;           // 0..56
                const float* pr = &Ps[(wid * 16 + srow) * PD + tloc];
                float4 v0 = *(const float4*)pr;
                float4 v1 = *(const float4*)(pr + 4);
                uint4 o;
                o.x = pkbf(v0.x, v0.y); o.y = pkbf(v0.z, v0.w);
                o.z = pkbf(v1.x, v1.y); o.w = pkbf(v1.z, v1.w);
                *(uint4*)(gp + (size_t)srow * S_LEN + tloc) = o;
            }
        }
        __syncthreads();
    }

    const float inv0 = 1.0f / l0, inv1 = 1.0f / l1;
    #pragma unroll
    for (int nt = 0; nt < 8; nt++) {
        size_t base0 = ((size_t)(s0 + R0) * BATCH + b) * EMB + h * HDIM + nt * 8 + 2 * q;
        size_t base1 = ((size_t)(s0 + R0 + 8) * BATCH + b) * EMB + h * HDIM + nt * 8 + 2 * q;
        *(float2*)&ctx[base0] = make_float2(acc[nt][0] * inv0, acc[nt][1] * inv0);
        *(float2*)&ctx[base1] = make_float2(acc[nt][2] * inv1, acc[nt][3] * inv1);
    }

    if (q == 0) {
        int base = (b * HEADS + h) * S_LEN + s0;
        g_lfv[base + R0]     = l0;
        g_lfv[base + R0 + 8] = l1;
    }
}

// ===========================================================================
// colsum kernel (bandwidth-bound): colsum[b,t] += sum_s spill[cta][s][t] / l_s
// One CTA per attention CTA; thread owns 4 t-columns; fully coalesced reads.
// ===========================================================================
__global__ __launch_bounds__(256) void colsum_kernel(float* __restrict__ colsum)
{
    __shared__ float wrow[128];
    const int sb = blockIdx.x, h = blockIdx.y, b = blockIdx.z;
    const int cta = (b * HEADS + h) * NSB + sb;
    const int tid = threadIdx.x;

    if (tid < 128)
        wrow[tid] = 1.0f / g_lfv[(b * HEADS + h) * S_LEN + sb * 128 + tid];
    __syncthreads();

    const int t = tid * 4;
    const __nv_bfloat16* base = g_ps + ((size_t)cta * 128) * S_LEN + t;
    float a0 = 0.f, a1 = 0.f, a2 = 0.f, a3 = 0.f;
    #pragma unroll 4
    for (int s = 0; s < 128; s++) {
        float w = wrow[s];
        uint2 v = *(const uint2*)(base + (size_t)s * S_LEN);
        float2 f01 = __bfloat1622float2(*(__nv_bfloat162*)&v.x);
        float2 f23 = __bfloat1622float2(*(__nv_bfloat162*)&v.y);
        a0 = fmaf(w, f01.x, a0);
        a1 = fmaf(w, f01.y, a1);
        a2 = fmaf(w, f23.x, a2);
        a3 = fmaf(w, f23.y, a3);
    }
    atomicAdd(&colsum[b * S_LEN + t + 0], a0);
    atomicAdd(&colsum[b * S_LEN + t + 1], a1);
    atomicAdd(&colsum[b * S_LEN + t + 2], a2);
    atomicAdd(&colsum[b * S_LEN + t + 3], a3);
}

// ===========================================================================
// wpool (256 CTAs): X[b,c] += sum over 128-t chunk
// ===========================================================================
__global__ __launch_bounds__(256) void wpool_kernel(
    const float* __restrict__ ctx, const float* __restrict__ colsum,
    float* __restrict__ X)
{
    const int b  = blockIdx.z;
    const int t0 = blockIdx.y * 128;
    const int c  = blockIdx.x * 256 + threadIdx.x;
    const float inv = 1.0f / ((float)S_LEN * (float)HEADS);
    float acc = 0.0f;
    #pragma unroll 4
    for (int t = t0; t < t0 + 128; t++) {
        float w = colsum[b * S_LEN + t] * inv;
        acc = fmaf(w, ctx[((size_t)t * BATCH + b) * EMB + c], acc);
    }
    atomicAdd(&X[b * EMB + c], acc);
}

// ===========================================================================
// gemv: out[b,e] = sum_c X[b,c]*W[e,c] + bias[e]
// ===========================================================================
__global__ __launch_bounds__(256) void gemv_kernel(
    const float* __restrict__ X, const float* __restrict__ W,
    const float* __restrict__ bias, float* __restrict__ out)
{
    const int wid  = threadIdx.x >> 5;
    const int lane = threadIdx.x & 31;
    const int e = blockIdx.x * 8 + wid;

    float acc[BATCH] = {};
    for (int c0 = lane * 4; c0 < EMB; c0 += 128) {
        float4 wv = *(const float4*)&W[(size_t)e * EMB + c0];
        #pragma unroll
        for (int b = 0; b < BATCH; b++) {
            float4 xv = *(const float4*)&X[b * EMB + c0];
            acc[b] += wv.x * xv.x + wv.y * xv.y + wv.z * xv.z + wv.w * xv.w;
        }
    }
    #pragma unroll
    for (int b = 0; b < BATCH; b++) {
        float v = acc[b];
        #pragma unroll
        for (int off = 16; off >= 1; off >>= 1)
            v += __shfl_xor_sync(0xffffffffu, v, off);
        if (lane == 0) out[b * EMB + e] = v + bias[e];
    }
}

// ===========================================================================
extern "C" void kernel_launch(void* const* d_in, const int* in_sizes, int n_in,
                              void* d_out, int out_size)
{
    const float* x     = (const float*)d_in[0];
    const float* w_in  = (const float*)d_in[1];
    const float* b_in  = (const float*)d_in[2];
    const float* w_out = (const float*)d_in[3];
    const float* b_out = (const float*)d_in[4];
    float* out = (float*)d_out;

    float *qkv_p, *ctx_p, *colsum_p, *X_p, *xc_p, *wc_p;
    cudaGetSymbolAddress((void**)&qkv_p,    g_qkv);
    cudaGetSymbolAddress((void**)&ctx_p,    g_ctx);
    cudaGetSymbolAddress((void**)&colsum_p, g_colsum);
    cudaGetSymbolAddress((void**)&X_p,      g_X);
    cudaGetSymbolAddress((void**)&xc_p,     g_xc);
    cudaGetSymbolAddress((void**)&wc_p,     g_wc);

    cudaFuncSetAttribute(attn_pass1, cudaFuncAttributeMaxDynamicSharedMemorySize,
                         P1_SMEM);
    cudaFuncSetAttribute(tc_gemm, cudaFuncAttributeMaxDynamicSharedMemorySize,
                         GEMM_SMEM);

    zero_kernel<<<32, 256>>>();

    // pre-convert GEMM operands to tf32 (once per element, in gmem)
    cvt_kernel<<<(MROWS * EMB / 4 + 255) / 256, 256>>>(
        (const float4*)x, (float4*)xc_p, MROWS * EMB / 4);
    cvt_kernel<<<(F3 * EMB / 4 + 255) / 256, 256>>>(
        (const float4*)w_in, (float4*)wc_p, F3 * EMB / 4);

    // QKV projection (tf32 mma.sync, R9 pipeline)
    tc_gemm<<<dim3(F3 / 128, MROWS / 128), 256, GEMM_SMEM>>>(
        xc_p, wc_p, b_in, qkv_p, MROWS, F3, EMB);

    // attention pass 1 (no-max): ctx + l + bf16 prob spill
    attn_pass1<<<dim3(NSB, HEADS, BATCH), 256, P1_SMEM>>>(qkv_p, ctx_p);

    // colsum from spilled probs (bandwidth-bound; replaces QK^T recompute)
    colsum_kernel<<<dim3(NSB, HEADS, BATCH), 256>>>(colsum_p);

    // weighted pooling of ctx (pool-before-projection; exact by linearity)
    wpool_kernel<<<dim3(EMB / 256, S_LEN / 128, BATCH), 256>>>(
        ctx_p, colsum_p, X_p);

    // tiny GEMV against w_out (+ bias, since weights sum to 1)
    gemv_kernel<<<EMB / 8, 256>>>(X_p, w_out, b_out, out);
}

// round 17
// speedup vs baseline: 1.2867x; 1.1319x over previous
#include <cuda_runtime.h>
#include <cuda_bf16.h>
#include <math.h>
#include <stdint.h>

// Problem constants (fixed shapes)
#define S_LEN 1024
#define BATCH 8
#define EMB   1024
#define HEADS 16
#define HDIM  64
#define MROWS (S_LEN * BATCH)   // 8192
#define F3    (3 * EMB)         // 3072
#define NSB   (S_LEN / 128)     // 8 s-blocks per (b,h)
#define NCTA  (BATCH * HEADS * NSB)  // 1024
#define NTILE 16                // 1024/64 t-tiles

// -------- scratch (__device__ globals; no cudaMalloc allowed) --------
__device__ float g_qkv[MROWS * F3];
__device__ float g_ctx[MROWS * EMB];
__device__ float g_colsum[BATCH * S_LEN];
__device__ float g_lfv[BATCH * HEADS * S_LEN];   // row sums (no-max softmax)
__device__ float g_X  [BATCH * EMB];             // weighted-pooled ctx
__device__ float g_xc [MROWS * EMB];             // tf32, fragment-major tiles
__device__ float g_wc [F3 * EMB];                // tf32, fragment-major tiles
__device__ __nv_bfloat16 g_ps[(size_t)NCTA * 128 * S_LEN];  // prob spill, 268MB

// ===========================================================================
// helpers
// ===========================================================================
__device__ __forceinline__ uint32_t smem_u32(const void* p) {
    return (uint32_t)__cvta_generic_to_shared(p);
}
#define CP_ASYNC16(dst, src) \
    asm volatile("cp.async.cg.shared.global [%0], [%1], 16;" :: "r"(dst), "l"(src))
#define CP_ASYNC_COMMIT() asm volatile("cp.async.commit_group;" ::: "memory")
#define CP_ASYNC_WAIT(n)  asm volatile("cp.async.wait_group %0;" :: "n"(n) : "memory")

__device__ __forceinline__ uint32_t f2tf32(float f) {
    uint32_t u;
    asm("cvt.rna.tf32.f32 %0, %1;" : "=r"(u) : "f"(f));
    return u;
}
__device__ __forceinline__ float tf32f(float f) {
    return __uint_as_float(f2tf32(f));
}
__device__ __forceinline__ uint32_t pkbf(float a, float b) {
    __nv_bfloat162 t = __floats2bfloat162_rn(a, b);
    return *(uint32_t*)&t;
}

__device__ __forceinline__ void mma_tf32(float* c, const uint32_t* a, const uint32_t* b) {
    asm volatile(
        "mma.sync.aligned.m16n8k8.row.col.f32.tf32.tf32.f32 "
        "{%0,%1,%2,%3}, {%4,%5,%6,%7}, {%8,%9}, {%0,%1,%2,%3};"
        : "+f"(c[0]), "+f"(c[1]), "+f"(c[2]), "+f"(c[3])
        : "r"(a[0]), "r"(a[1]), "r"(a[2]), "r"(a[3]), "r"(b[0]), "r"(b[1]));
}

// ===========================================================================
// zero kernel: colsum + X
// ===========================================================================
__global__ void zero_kernel() {
    int i = blockIdx.x * 256 + threadIdx.x;
    if (i < BATCH * S_LEN) g_colsum[i] = 0.0f;
    if (i < BATCH * EMB)   g_X[i] = 0.0f;
}

// ===========================================================================
// permuting tf32 converts: emit fragment-major 128x32 tile blocks.
// A block layout (4096 floats): [band16(8)][ks(4)][qrow(8)][qcol(4)][frag(4)]
//   frag f -> src (row = band16*16 + (f&1)*8 + qrow, k = ks*8 + (f>>1)*4 + qcol)
// B block layout (4096 floats): [b8(16)][ks(4)][qrow(8)][qcol(4)][pair(2)]
//   pair p -> src (row = b8*8 + qrow, k = ks*8 + p*4 + qcol)
// grid: (rows/128) x (K/32); 256 threads; smem-staged, coalesced both ways.
// Tile = 128x32 = 4096 floats -> 4 load iterations of 1024 floats.
// ===========================================================================
__global__ __launch_bounds__(256) void cvt_permA(
    const float* __restrict__ src, float* __restrict__ dst, int K)
{
    __shared__ float sm[128][33];
    const int mb = blockIdx.x, kt = blockIdx.y;
    const int t = threadIdx.x;
    const int nkt = gridDim.y;

    #pragma unroll
    for (int i = 0; i < 4; i++) {
        int linear = i * 1024 + t * 4;         // 0..4092
        int row = linear >> 5, c = linear & 31;
        float4 v = *(const float4*)&src[(size_t)(mb * 128 + row) * K + kt * 32 + c];
        sm[row][c]     = tf32f(v.x);
        sm[row][c + 1] = tf32f(v.y);
        sm[row][c + 2] = tf32f(v.z);
        sm[row][c + 3] = tf32f(v.w);
    }
    __syncthreads();

    float* out = dst + ((size_t)mb * nkt + kt) * 4096;
    #pragma unroll
    for (int i = 0; i < 4; i++) {
        int qidx = i * 256 + t;                // 0..1023 fragment quads
        int qcol = qidx & 3;
        int qrow = (qidx >> 2) & 7;
        int ks   = (qidx >> 5) & 3;
        int b16  = qidx >> 7;
        float4 o;
        o.x = sm[b16 * 16 + qrow][ks * 8 + qcol];
        o.y = sm[b16 * 16 + 8 + qrow][ks * 8 + qcol];
        o.z = sm[b16 * 16 + qrow][ks * 8 + 4 + qcol];
        o.w = sm[b16 * 16 + 8 + qrow][ks * 8 + 4 + qcol];
        *(float4*)&out[qidx * 4] = o;
    }
}

__global__ __launch_bounds__(256) void cvt_permB(
    const float* __restrict__ src, float* __restrict__ dst, int K)
{
    __shared__ float sm[128][33];
    const int nb = blockIdx.x, kt = blockIdx.y;
    const int t = threadIdx.x;
    const int nkt = gridDim.y;

    #pragma unroll
    for (int i = 0; i < 4; i++) {
        int linear = i * 1024 + t * 4;         // 0..4092
        int row = linear >> 5, c = linear & 31;
        float4 v = *(const float4*)&src[(size_t)(nb * 128 + row) * K + kt * 32 + c];
        sm[row][c]     = tf32f(v.x);
        sm[row][c + 1] = tf32f(v.y);
        sm[row][c + 2] = tf32f(v.z);
        sm[row][c + 3] = tf32f(v.w);
    }
    __syncthreads();

    float* out = dst + ((size_t)nb * nkt + kt) * 4096;
    #pragma unroll
    for (int i = 0; i < 8; i++) {
        int pidx = i * 256 + t;                // 0..2047 fragment pairs
        int qcol = pidx & 3;
        int qrow = (pidx >> 2) & 7;
        int ks   = (pidx >> 5) & 3;
        int b8   = pidx >> 7;
        float2 o;
        o.x = sm[b8 * 8 + qrow][ks * 8 + qcol];
        o.y = sm[b8 * 8 + qrow][ks * 8 + 4 + qcol];
        *(float2*)&out[pidx * 2] = o;
    }
}

// ===========================================================================
// tf32 tensor-core GEMM, fragment-major operands.
// 128x128 tile, BK=32, 3-stage cp.async, single sync/k-tile.
// Inner loop: 4 LDS.128 (A) + 4 LDS.64 (B) + 16 MMA per ks.
// smem = 3 * 32KB = 96KB (no padding needed).
// ===========================================================================
#define TSTAGES 3
#define TBK 32
#define BLK_FLOATS 4096                       // one 128x32 operand block
#define STAGE_FLOATS (2 * BLK_FLOATS)         // A + B
#define STAGE_BYTES (STAGE_FLOATS * 4)        // 32768
#define GEMM_SMEM (TSTAGES * STAGE_BYTES)     // 98304

__global__ __launch_bounds__(256) void tc_gemm(
    const float* __restrict__ A, const float* __restrict__ B,
    const float* __restrict__ bias, float* __restrict__ C,
    int M, int N, int K)
{
    extern __shared__ __align__(16) float smem[];
    const uint32_t sbase = smem_u32(smem);

    const int tid  = threadIdx.x;
    const int wid  = tid >> 5;
    const int lane = tid & 31;
    const int wr = wid >> 2;          // 0..1
    const int wc = wid & 3;           // 0..3
    const int qrow = lane >> 2;       // 0..7
    const int qcol = lane & 3;        // 0..3

    const int KT = K / TBK;
    const float* Atile = A + (size_t)blockIdx.y * KT * BLK_FLOATS;
    const float* Btile = B + (size_t)blockIdx.x * KT * BLK_FLOATS;
    const int m0 = blockIdx.y * 128;
    const int n0 = blockIdx.x * 128;

    // loader: thread t copies 64B of A and 64B of B per stage (sequential)
    const uint32_t sA = sbase + tid * 64;
    const uint32_t sB = sbase + BLK_FLOATS * 4 + tid * 64;

    #pragma unroll
    for (int p = 0; p < TSTAGES - 1; p++) {
        uint32_t so = (uint32_t)(p * STAGE_BYTES);
        const float* as = Atile + p * BLK_FLOATS + tid * 16;
        const float* bs = Btile + p * BLK_FLOATS + tid * 16;
        #pragma unroll
        for (int i = 0; i < 4; i++) {
            CP_ASYNC16(sA + so + i * 16, as + i * 4);
            CP_ASYNC16(sB + so + i * 16, bs + i * 4);
        }
        CP_ASYNC_COMMIT();
    }

    float acc[4][4][4] = {};

    for (int kt = 0; kt < KT; kt++) {
        if (kt < KT - 1) { CP_ASYNC_WAIT(1); } else { CP_ASYNC_WAIT(0); }
        __syncthreads();

        if (kt + 2 < KT) {
            uint32_t so = (uint32_t)(((kt + 2) % TSTAGES) * STAGE_BYTES);
            const float* as = Atile + (kt + 2) * BLK_FLOATS + tid * 16;
            const float* bs = Btile + (kt + 2) * BLK_FLOATS + tid * 16;
            #pragma unroll
            for (int i = 0; i < 4; i++) {
                CP_ASYNC16(sA + so + i * 16, as + i * 4);
                CP_ASYNC16(sB + so + i * 16, bs + i * 4);
            }
            CP_ASYNC_COMMIT();
        }

        const float* As = smem + (kt % TSTAGES) * STAGE_FLOATS;
        const float* Bs = As + BLK_FLOATS;

        #pragma unroll
        for (int ks = 0; ks < 4; ks++) {
            uint32_t afr[4][4];
            uint32_t bfr[4][2];
            #pragma unroll
            for (int mt = 0; mt < 4; mt++) {
                int b16 = wr * 4 + mt;
                const float4 av = *(const float4*)
                    &As[(((b16 * 4 + ks) * 8 + qrow) * 4 + qcol) * 4];
                afr[mt][0] = __float_as_uint(av.x);
                afr[mt][1] = __float_as_uint(av.y);
                afr[mt][2] = __float_as_uint(av.z);
                afr[mt][3] = __float_as_uint(av.w);
            }
            #pragma unroll
            for (int nt = 0; nt < 4; nt++) {
                int b8 = wc * 4 + nt;
                const float2 bv = *(const float2*)
                    &Bs[(((b8 * 4 + ks) * 8 + qrow) * 4 + qcol) * 2];
                bfr[nt][0] = __float_as_uint(bv.x);
                bfr[nt][1] = __float_as_uint(bv.y);
            }
            #pragma unroll
            for (int mt = 0; mt < 4; mt++)
                #pragma unroll
                for (int nt = 0; nt < 4; nt++)
                    mma_tf32(acc[mt][nt], afr[mt], bfr[nt]);
        }
    }

    __syncthreads();
    #pragma unroll
    for (int mt = 0; mt < 4; mt++) {
        int row = m0 + wr * 64 + mt * 16 + qrow;
        #pragma unroll
        for (int nt = 0; nt < 4; nt++) {
            int col = n0 + wc * 32 + nt * 8 + 2 * qcol;
            float b0 = bias[col], b1 = bias[col + 1];
            float2 o0 = make_float2(acc[mt][nt][0] + b0, acc[mt][nt][1] + b1);
            float2 o1 = make_float2(acc[mt][nt][2] + b0, acc[mt][nt][3] + b1);
            *(float2*)&C[(size_t)row * N + col] = o0;
            *(float2*)&C[(size_t)(row + 8) * N + col] = o1;
        }
    }
}

// ===========================================================================
// Attention pass 1 (no-max softmax, R15 version): unnormalized U and l;
// ctx = U/l; spills unnormalized probs to global as bf16.
// ===========================================================================
#define QD 68
#define KD 68
#define VD 72
#define PD 68
#define P1_SMEM ((128*QD + 64*KD + 64*VD + 128*PD) * 4)

__global__ __launch_bounds__(256, 2) void attn_pass1(
    const float* __restrict__ qkv, float* __restrict__ ctx)
{
    extern __shared__ __align__(16) float sm[];
    float* Qs = sm;
    float* Ks = Qs + 128 * QD;
    float* Vs = Ks + 64 * KD;
    float* Ps = Vs + 64 * VD;

    const int tid  = threadIdx.x;
    const int wid  = tid >> 5;
    const int lane = tid & 31;
    const int qrow = lane >> 2;
    const int q    = lane & 3;
    const int sb = blockIdx.x, h = blockIdx.y, b = blockIdx.z;
    const int s0 = sb * 128;
    const int cta = (b * HEADS + h) * NSB + sb;
    const int R0 = wid * 16 + qrow;

    for (int idx = tid; idx < 128 * 16; idx += 256) {
        int row = idx >> 4, c = idx & 15;
        float4 v = *(const float4*)&qkv[((size_t)(s0 + row) * BATCH + b) * F3 + h * HDIM + c * 4];
        float4 o = make_float4(tf32f(v.x * 0.125f), tf32f(v.y * 0.125f),
                               tf32f(v.z * 0.125f), tf32f(v.w * 0.125f));
        *(float4*)&Qs[row * QD + c * 4] = o;
    }

    float l0 = 0.0f, l1 = 0.0f;
    float acc[8][4] = {};
    __syncthreads();

    for (int tb = 0; tb < NTILE; tb++) {
        const int t0 = tb * 64;
        for (int idx = tid; idx < 64 * 16; idx += 256) {
            int row = idx >> 4, c = idx & 15;
            const float* base = &qkv[((size_t)(t0 + row) * BATCH + b) * F3 + h * HDIM + c * 4];
            float4 kv = *(const float4*)(base + EMB);
            float4 vv = *(const float4*)(base + 2 * EMB);
            *(float4*)&Ks[row * KD + c * 4] =
                make_float4(tf32f(kv.x), tf32f(kv.y), tf32f(kv.z), tf32f(kv.w));
            *(float4*)&Vs[row * VD + c * 4] =
                make_float4(tf32f(vv.x), tf32f(vv.y), tf32f(vv.z), tf32f(vv.w));
        }
        __syncthreads();

        float sf[8][4] = {};
        #pragma unroll
        for (int ks = 0; ks < 8; ks++) {
            const int kq = ks * 8 + q;
            uint32_t a[4];
            a[0] = __float_as_uint(Qs[R0 * QD + kq]);
            a[1] = __float_as_uint(Qs[(R0 + 8) * QD + kq]);
            a[2] = __float_as_uint(Qs[R0 * QD + kq + 4]);
            a[3] = __float_as_uint(Qs[(R0 + 8) * QD + kq + 4]);
            #pragma unroll
            for (int nt = 0; nt < 8; nt++) {
                uint32_t bb[2];
                bb[0] = __float_as_uint(Ks[(nt * 8 + qrow) * KD + kq]);
                bb[1] = __float_as_uint(Ks[(nt * 8 + qrow) * KD + kq + 4]);
                mma_tf32(sf[nt], a, bb);
            }
        }

        float rs0 = 0.0f, rs1 = 0.0f;
        #pragma unroll
        for (int nt = 0; nt < 8; nt++) {
            float p0 = __expf(sf[nt][0]);
            float p1 = __expf(sf[nt][1]);
            float p2 = __expf(sf[nt][2]);
            float p3 = __expf(sf[nt][3]);
            rs0 += p0 + p1;
            rs1 += p2 + p3;
            *(float2*)&Ps[R0 * PD + nt * 8 + 2 * q] =
                make_float2(tf32f(p0), tf32f(p1));
            *(float2*)&Ps[(R0 + 8) * PD + nt * 8 + 2 * q] =
                make_float2(tf32f(p2), tf32f(p3));
        }
        rs0 += __shfl_xor_sync(0xffffffffu, rs0, 1);
        rs0 += __shfl_xor_sync(0xffffffffu, rs0, 2);
        rs1 += __shfl_xor_sync(0xffffffffu, rs1, 1);
        rs1 += __shfl_xor_sync(0xffffffffu, rs1, 2);
        l0 += rs0;
        l1 += rs1;
        __syncwarp();

        // U += P @ V (unnormalized)
        #pragma unroll
        for (int ks = 0; ks < 8; ks++) {
            const int kq = ks * 8 + q;
            uint32_t a[4];
            a[0] = __float_as_uint(Ps[R0 * PD + kq]);
            a[1] = __float_as_uint(Ps[(R0 + 8) * PD + kq]);
            a[2] = __float_as_uint(Ps[R0 * PD + kq + 4]);
            a[3] = __float_as_uint(Ps[(R0 + 8) * PD + kq + 4]);
            #pragma unroll
            for (int nt = 0; nt < 8; nt++) {
                uint32_t bb[2];
                bb[0] = __float_as_uint(Vs[kq * VD + nt * 8 + qrow]);
                bb[1] = __float_as_uint(Vs[(kq + 4) * VD + nt * 8 + qrow]);
                mma_tf32(acc[nt], a, bb);
            }
        }

        // spill own-warp probs (16 rows x 64 t) as bf16, coalesced
        {
            __nv_bfloat16* gp = g_ps + ((size_t)cta * 128 + wid * 16) * S_LEN + t0;
            #pragma unroll
            for (int j = 0; j < 4; j++) {
                int srow = j * 4 + (lane >> 3);
                int tloc = (lane & 7) * 8;
                const float* pr = &Ps[(wid * 16 + srow) * PD + tloc];
                float4 v0 = *(const float4*)pr;
                float4 v1 = *(const float4*)(pr + 4);
                uint4 o;
                o.x = pkbf(v0.x, v0.y); o.y = pkbf(v0.z, v0.w);
                o.z = pkbf(v1.x, v1.y); o.w = pkbf(v1.z, v1.w);
                *(uint4*)(gp + (size_t)srow * S_LEN + tloc) = o;
            }
        }
        __syncthreads();
    }

    const float inv0 = 1.0f / l0, inv1 = 1.0f / l1;
    #pragma unroll
    for (int nt = 0; nt < 8; nt++) {
        size_t base0 = ((size_t)(s0 + R0) * BATCH + b) * EMB + h * HDIM + nt * 8 + 2 * q;
        size_t base1 = ((size_t)(s0 + R0 + 8) * BATCH + b) * EMB + h * HDIM + nt * 8 + 2 * q;
        *(float2*)&ctx[base0] = make_float2(acc[nt][0] * inv0, acc[nt][1] * inv0);
        *(float2*)&ctx[base1] = make_float2(acc[nt][2] * inv1, acc[nt][3] * inv1);
    }

    if (q == 0) {
        int base = (b * HEADS + h) * S_LEN + s0;
        g_lfv[base + R0]     = l0;
        g_lfv[base + R0 + 8] = l1;
    }
}

// ===========================================================================
// colsum kernel (bandwidth-bound, R15 version)
// ===========================================================================
__global__ __launch_bounds__(256) void colsum_kernel(float* __restrict__ colsum)
{
    __shared__ float wrow[128];
    const int sb = blockIdx.x, h = blockIdx.y, b = blockIdx.z;
    const int cta = (b * HEADS + h) * NSB + sb;
    const int tid = threadIdx.x;

    if (tid < 128)
        wrow[tid] = 1.0f / g_lfv[(b * HEADS + h) * S_LEN + sb * 128 + tid];
    __syncthreads();

    const int t = tid * 4;
    const __nv_bfloat16* base = g_ps + ((size_t)cta * 128) * S_LEN + t;
    float a0 = 0.f, a1 = 0.f, a2 = 0.f, a3 = 0.f;
    #pragma unroll 4
    for (int s = 0; s < 128; s++) {
        float w = wrow[s];
        uint2 v = *(const uint2*)(base + (size_t)s * S_LEN);
        float2 f01 = __bfloat1622float2(*(__nv_bfloat162*)&v.x);
        float2 f23 = __bfloat1622float2(*(__nv_bfloat162*)&v.y);
        a0 = fmaf(w, f01.x, a0);
        a1 = fmaf(w, f01.y, a1);
        a2 = fmaf(w, f23.x, a2);
        a3 = fmaf(w, f23.y, a3);
    }
    atomicAdd(&colsum[b * S_LEN + t + 0], a0);
    atomicAdd(&colsum[b * S_LEN + t + 1], a1);
    atomicAdd(&colsum[b * S_LEN + t + 2], a2);
    atomicAdd(&colsum[b * S_LEN + t + 3], a3);
}

// ===========================================================================
// wpool (256 CTAs): X[b,c] += sum over 128-t chunk
// ===========================================================================
__global__ __launch_bounds__(256) void wpool_kernel(
    const float* __restrict__ ctx, const float* __restrict__ colsum,
    float* __restrict__ X)
{
    const int b  = blockIdx.z;
    const int t0 = blockIdx.y * 128;
    const int c  = blockIdx.x * 256 + threadIdx.x;
    const float inv = 1.0f / ((float)S_LEN * (float)HEADS);
    float acc = 0.0f;
    #pragma unroll 4
    for (int t = t0; t < t0 + 128; t++) {
        float w = colsum[b * S_LEN + t] * inv;
        acc = fmaf(w, ctx[((size_t)t * BATCH + b) * EMB + c], acc);
    }
    atomicAdd(&X[b * EMB + c], acc);
}

// ===========================================================================
// gemv: out[b,e] = sum_c X[b,c]*W[e,c] + bias[e]
// ===========================================================================
__global__ __launch_bounds__(256) void gemv_kernel(
    const float* __restrict__ X, const float* __restrict__ W,
    const float* __restrict__ bias, float* __restrict__ out)
{
    const int wid  = threadIdx.x >> 5;
    const int lane = threadIdx.x & 31;
    const int e = blockIdx.x * 8 + wid;

    float acc[BATCH] = {};
    for (int c0 = lane * 4; c0 < EMB; c0 += 128) {
        float4 wv = *(const float4*)&W[(size_t)e * EMB + c0];
        #pragma unroll
        for (int b = 0; b < BATCH; b++) {
            float4 xv = *(const float4*)&X[b * EMB + c0];
            acc[b] += wv.x * xv.x + wv.y * xv.y + wv.z * xv.z + wv.w * xv.w;
        }
    }
    #pragma unroll
    for (int b = 0; b < BATCH; b++) {
        float v = acc[b];
        #pragma unroll
        for (int off = 16; off >= 1; off >>= 1)
            v += __shfl_xor_sync(0xffffffffu, v, off);
        if (lane == 0) out[b * EMB + e] = v + bias[e];
    }
}

// ===========================================================================
extern "C" void kernel_launch(void* const* d_in, const int* in_sizes, int n_in,
                              void* d_out, int out_size)
{
    const float* x     = (const float*)d_in[0];
    const float* w_in  = (const float*)d_in[1];
    const float* b_in  = (const float*)d_in[2];
    const float* w_out = (const float*)d_in[3];
    const float* b_out = (const float*)d_in[4];
    float* out = (float*)d_out;

    float *qkv_p, *ctx_p, *colsum_p, *X_p, *xc_p, *wc_p;
    cudaGetSymbolAddress((void**)&qkv_p,    g_qkv);
    cudaGetSymbolAddress((void**)&ctx_p,    g_ctx);
    cudaGetSymbolAddress((void**)&colsum_p, g_colsum);
    cudaGetSymbolAddress((void**)&X_p,      g_X);
    cudaGetSymbolAddress((void**)&xc_p,     g_xc);
    cudaGetSymbolAddress((void**)&wc_p,     g_wc);

    cudaFuncSetAttribute(attn_pass1, cudaFuncAttributeMaxDynamicSharedMemorySize,
                         P1_SMEM);
    cudaFuncSetAttribute(tc_gemm, cudaFuncAttributeMaxDynamicSharedMemorySize,
                         GEMM_SMEM);

    zero_kernel<<<32, 256>>>();

    // permuting tf32 converts: fragment-major tile blocks
    cvt_permA<<<dim3(MROWS / 128, EMB / 32), 256>>>(x, xc_p, EMB);
    cvt_permB<<<dim3(F3 / 128, EMB / 32), 256>>>(w_in, wc_p, EMB);

    // QKV projection (tf32 mma.sync, fragment-major operands)
    tc_gemm<<<dim3(F3 / 128, MROWS / 128), 256, GEMM_SMEM>>>(
        xc_p, wc_p, b_in, qkv_p, MROWS, F3, EMB);

    // attention pass 1 (no-max): ctx + l + bf16 prob spill
    attn_pass1<<<dim3(NSB, HEADS, BATCH), 256, P1_SMEM>>>(qkv_p, ctx_p);

    // colsum from spilled probs (bandwidth-bound)
    colsum_kernel<<<dim3(NSB, HEADS, BATCH), 256>>>(colsum_p);

    // weighted pooling of ctx (pool-before-projection; exact by linearity)
    wpool_kernel<<<dim3(EMB / 256, S_LEN / 128, BATCH), 256>>>(
        ctx_p, colsum_p, X_p);

    // tiny GEMV against w_out (+ bias, since weights sum to 1)
    gemv_kernel<<<EMB / 8, 256>>>(X_p, w_out, b_out, out);
}